// round 3
// baseline (speedup 1.0000x reference)
#include <cuda_runtime.h>
#include <cstdint>

// Problem constants (from reference)
#define PCR0      (-51.2f)
#define VX        (0.05f)
#define STRIDE_F  (4.0f)
#define FW        512
#define FH        512
#define NUM_CLASSES 10
#define NUM_MAX_OBJS 500
#define BATCH     16
#define OVERLAP   (0.1f)
#define MIN_RADIUS 2
#define RMAX      16
#define EPS_F32   (1.1920929e-07f)

#define HEAT_ELEMS   ((size_t)BATCH * NUM_CLASSES * FH * FW)
#define BOXES_ELEMS  ((size_t)BATCH * NUM_MAX_OBJS * 8)
#define INDS_ELEMS   ((size_t)BATCH * NUM_MAX_OBJS)

#define TOBJ   (BATCH * NUM_MAX_OBJS)     // 8000
#define NTY    16                          // 512 / 32
#define NTX    16
#define NTILE  (BATCH * NUM_CLASSES * NTY * NTX)   // 40960
#define CAP    128                         // max objects listed per tile

// Static device scratch (no dynamic allocation)
__device__ int   d_cnt [NTILE];
__device__ int   d_list[NTILE * CAP];
__device__ float d_exp [TOBJ * (RMAX + 1)];
__device__ int4  d_meta[TOBJ];             // {cxi, cyi, r, valid}

__device__ __forceinline__ float gaussian_radius(float h, float w, float ov) {
    float b1 = h + w;
    float c1 = w * h * (1.0f - ov) / (1.0f + ov);
    float sq1 = sqrtf(fmaxf(b1 * b1 - 4.0f * c1, 0.0f));
    float r1 = (b1 + sq1) * 0.5f;

    float b2 = 2.0f * (h + w);
    float c2 = (1.0f - ov) * w * h;
    float sq2 = sqrtf(fmaxf(b2 * b2 - 16.0f * c2, 0.0f));
    float r2 = (b2 + sq2) * 0.5f;

    float a3 = 4.0f * ov;
    float b3 = -2.0f * ov * (h + w);
    float c3 = (ov - 1.0f) * w * h;
    float sq3 = sqrtf(fmaxf(b3 * b3 - 4.0f * a3 * c3, 0.0f));
    float r3 = (b3 + sq3) / (2.0f * a3);

    return fminf(fminf(r1, r2), r3);
}

// One thread per object: compute params, emit exp table + meta, bin into
// tile lists, and write the per-object outputs (boxes / inds / mask).
__global__ void bin_kernel(const float* __restrict__ gt,
                           float* __restrict__ boxes,
                           float* __restrict__ inds,
                           float* __restrict__ mask)
{
    const int obj = blockIdx.x * blockDim.x + threadIdx.x;
    if (obj >= TOBJ) return;
    const int b = obj / NUM_MAX_OBJS;

    const float* g = gt + (size_t)obj * 8;
    const float x  = g[0], y  = g[1], z  = g[2];
    const float dx = g[3], dy = g[4], dz = g[5];
    const float hd = g[6];
    const int   cls = (int)(g[7] - 1.0f);

    float coord_x = (x - PCR0) / VX / STRIDE_F;
    float coord_y = (y - PCR0) / VX / STRIDE_F;
    coord_x = fminf(fmaxf(coord_x, 0.0f), (float)FW - 0.5f);
    coord_y = fminf(fmaxf(coord_y, 0.0f), (float)FH - 0.5f);
    const int cxi = (int)coord_x;
    const int cyi = (int)coord_y;

    const float dxf = dx / VX / STRIDE_F;
    const float dyf = dy / VX / STRIDE_F;

    int r = (int)gaussian_radius(dxf, dyf, OVERLAP);
    r = min(max(r, MIN_RADIUS), RMAX);

    const bool valid = (dxf > 0.0f) && (dyf > 0.0f) &&
                       (cxi >= 0) && (cxi <= FW) &&
                       (cyi >= 0) && (cyi <= FH);

    // per-object outputs
    {
        const float vf = valid ? 1.0f : 0.0f;
        float* bo = boxes + (size_t)obj * 8;
        bo[0] = (coord_x - (float)cxi) * vf;
        bo[1] = (coord_y - (float)cyi) * vf;
        bo[2] = z * vf;
        bo[3] = logf(fmaxf(dx, 1e-12f)) * vf;
        bo[4] = logf(fmaxf(dy, 1e-12f)) * vf;
        bo[5] = logf(fmaxf(dz, 1e-12f)) * vf;
        bo[6] = cosf(hd) * vf;
        bo[7] = sinf(hd) * vf;
        inds[obj] = valid ? (float)(cyi * FW + cxi) : 0.0f;
        mask[obj] = vf;
    }

    if (!valid) return;

    // 1D gaussian factor table
    const float sigma  = (2.0f * (float)r + 1.0f) / 6.0f;
    const float inv2s2 = 1.0f / (2.0f * sigma * sigma);
    float* tab = &d_exp[obj * (RMAX + 1)];
    for (int k = 0; k <= r; k++)
        tab[k] = expf(-(float)(k * k) * inv2s2);

    d_meta[obj] = make_int4(cxi, cyi, r, 1);

    // bin into intersecting tiles
    const int c = min(max(cls, 0), NUM_CLASSES - 1);
    const int ty0 = max(cyi - r, 0) >> 5;
    const int ty1 = min(cyi + r, FH - 1) >> 5;
    const int tx0 = max(cxi - r, 0) >> 5;
    const int tx1 = min(cxi + r, FW - 1) >> 5;
    const int pbase = (b * NUM_CLASSES + c) * NTY * NTX;
    for (int ty = ty0; ty <= ty1; ty++)
        for (int tx = tx0; tx <= tx1; tx++) {
            const int t = pbase + ty * NTX + tx;
            const int idx = atomicAdd(&d_cnt[t], 1);
            if (idx < CAP) d_list[t * CAP + idx] = obj;
        }
}

// One block per (batch, class, 32x32 tile). Each thread produces 4
// consecutive pixels (one float4 store). The store doubles as zero-init.
__global__ void __launch_bounds__(256) gather_kernel(float* __restrict__ heat)
{
    const int blk = blockIdx.x;
    const int tx  = blk & (NTX - 1);
    const int ty  = (blk >> 4) & (NTY - 1);
    const int pc  = blk >> 8;                  // b*NUM_CLASSES + c

    const int row = threadIdx.x >> 3;          // 0..31
    const int xq  = (threadIdx.x & 7) << 2;    // 0,4,...,28
    const int y   = (ty << 5) + row;
    const int x0  = (tx << 5) + xq;

    float4 acc = make_float4(0.f, 0.f, 0.f, 0.f);
    const int n = min(d_cnt[blk], CAP);

    for (int i = 0; i < n; i++) {
        const int o = d_list[blk * CAP + i];
        const int4 m = d_meta[o];              // cxi, cyi, r
        const int ady = abs(y - m.y);
        if (ady > m.z) continue;
        const float* tab = &d_exp[o * (RMAX + 1)];
        const float fi = __ldg(&tab[ady]);
        #pragma unroll
        for (int k = 0; k < 4; k++) {
            const int adx = abs(x0 + k - m.x);
            if (adx <= m.z) {
                const float v = fi * __ldg(&tab[adx]);
                if (v >= EPS_F32) {
                    float* a = ((float*)&acc) + k;
                    *a = fmaxf(*a, v);
                }
            }
        }
    }

    float* plane = heat + (size_t)pc * FH * FW;
    *(float4*)&plane[(size_t)y * FW + x0] = acc;
}

extern "C" void kernel_launch(void* const* d_in, const int* in_sizes, int n_in,
                              void* d_out, int out_size) {
    const float* gt = (const float*)d_in[0];
    float* out = (float*)d_out;

    float* heat  = out;
    float* boxes = out + HEAT_ELEMS;
    float* inds  = out + HEAT_ELEMS + BOXES_ELEMS;
    float* mask  = out + HEAT_ELEMS + BOXES_ELEMS + INDS_ELEMS;

    static int* cnt_ptr = nullptr;
    if (cnt_ptr == nullptr)
        cudaGetSymbolAddress((void**)&cnt_ptr, d_cnt);

    cudaMemsetAsync(cnt_ptr, 0, NTILE * sizeof(int));
    bin_kernel<<<(TOBJ + 255) / 256, 256>>>(gt, boxes, inds, mask);
    gather_kernel<<<NTILE, 256>>>(heat);
}

// round 4
// speedup vs baseline: 1.3896x; 1.3896x over previous
#include <cuda_runtime.h>
#include <cstdint>

// Problem constants (from reference)
#define PCR0      (-51.2f)
#define VX        (0.05f)
#define STRIDE_F  (4.0f)
#define FW        512
#define FH        512
#define NUM_CLASSES 10
#define NUM_MAX_OBJS 500
#define BATCH     16
#define OVERLAP   (0.1f)
#define MIN_RADIUS 2
#define RMAX      16
#define EPS_F32   (1.1920929e-07f)

// Output layout (float32, concatenated in reference-return order)
#define HEAT_ELEMS   ((size_t)BATCH * NUM_CLASSES * FH * FW)   // 41,943,040
#define BOXES_ELEMS  ((size_t)BATCH * NUM_MAX_OBJS * 8)        // 64,000
#define INDS_ELEMS   ((size_t)BATCH * NUM_MAX_OBJS)            // 8,000

// 2-way pipeline: memset chunk i on origin stream, splat chunk i on s1
#define NCHUNK    2
#define B_PER     (BATCH / NCHUNK)   // 8 batches per chunk -> grid 4000

__device__ __forceinline__ float gaussian_radius(float h, float w, float ov) {
    float b1 = h + w;
    float c1 = w * h * (1.0f - ov) / (1.0f + ov);
    float sq1 = sqrtf(fmaxf(b1 * b1 - 4.0f * c1, 0.0f));
    float r1 = (b1 + sq1) * 0.5f;

    float b2 = 2.0f * (h + w);
    float c2 = (1.0f - ov) * w * h;
    float sq2 = sqrtf(fmaxf(b2 * b2 - 16.0f * c2, 0.0f));
    float r2 = (b2 + sq2) * 0.5f;

    float a3 = 4.0f * ov;
    float b3 = -2.0f * ov * (h + w);
    float c3 = (ov - 1.0f) * w * h;
    float sq3 = sqrtf(fmaxf(b3 * b3 - 4.0f * a3 * c3, 0.0f));
    float r3 = (b3 + sq3) / (2.0f * a3);

    return fminf(fminf(r1, r2), r3);
}

__global__ void __launch_bounds__(128) splat_kernel(
        const float* __restrict__ gt,
        float* __restrict__ heat,
        float* __restrict__ boxes,
        float* __restrict__ inds,
        float* __restrict__ mask,
        int b0)  // first batch handled by this chunk
{
    const int obj = b0 * NUM_MAX_OBJS + blockIdx.x;
    const int b   = obj / NUM_MAX_OBJS;

    const float* g = gt + (size_t)obj * 8;
    const float x  = g[0], y  = g[1], z  = g[2];
    const float dx = g[3], dy = g[4], dz = g[5];
    const float hd = g[6];
    const int   cls = (int)(g[7] - 1.0f);

    float coord_x = (x - PCR0) / VX / STRIDE_F;
    float coord_y = (y - PCR0) / VX / STRIDE_F;
    coord_x = fminf(fmaxf(coord_x, 0.0f), (float)FW - 0.5f);
    coord_y = fminf(fmaxf(coord_y, 0.0f), (float)FH - 0.5f);
    const int cxi = (int)coord_x;
    const int cyi = (int)coord_y;

    const float dxf = dx / VX / STRIDE_F;
    const float dyf = dy / VX / STRIDE_F;

    int r = (int)gaussian_radius(dxf, dyf, OVERLAP);
    r = min(max(r, MIN_RADIUS), RMAX);

    const bool valid = (dxf > 0.0f) && (dyf > 0.0f) &&
                       (cxi >= 0) && (cxi <= FW) &&
                       (cyi >= 0) && (cyi <= FH);

    if (threadIdx.x == 0) {
        const float vf = valid ? 1.0f : 0.0f;
        float* bo = boxes + (size_t)obj * 8;
        bo[0] = (coord_x - (float)cxi) * vf;
        bo[1] = (coord_y - (float)cyi) * vf;
        bo[2] = z * vf;
        bo[3] = logf(fmaxf(dx, 1e-12f)) * vf;
        bo[4] = logf(fmaxf(dy, 1e-12f)) * vf;
        bo[5] = logf(fmaxf(dz, 1e-12f)) * vf;
        bo[6] = cosf(hd) * vf;
        bo[7] = sinf(hd) * vf;
        inds[obj] = valid ? (float)(cyi * FW + cxi) : 0.0f;
        mask[obj] = vf;
    }

    // 1D Gaussian factor table: ex[k] = exp(-k^2 / (2 sigma^2)), k = 0..r
    __shared__ float exs[RMAX + 1];
    const float sigma  = (2.0f * (float)r + 1.0f) / 6.0f;
    const float inv2s2 = 1.0f / (2.0f * sigma * sigma);
    if (threadIdx.x <= (unsigned)r) {
        const float k = (float)threadIdx.x;
        exs[threadIdx.x] = expf(-(k * k) * inv2s2);
    }
    __syncthreads();

    if (!valid) return;   // block-uniform

    const int c = min(max(cls, 0), NUM_CLASSES - 1);
    float* plane = heat + ((size_t)(b * NUM_CLASSES + c) * FH) * FW;

    const int side = 2 * r + 1;       // <= 33
    const int lane = threadIdx.x & 31;
    const int warp = threadIdx.x >> 5;

    // lane -> column offset(s); warp -> rows (strided by 4 warps)
    const int   oj0 = lane - r;
    const bool  c0  = (lane < side);
    const float fj0 = c0 ? exs[abs(oj0)] : 0.0f;
    const int   oj1 = lane + 32 - r;                 // only when side == 33
    const bool  c1  = (lane + 32 < side);
    const float fj1 = c1 ? exs[abs(oj1)] : 0.0f;

    for (int row = warp; row < side; row += 4) {
        const int oi = row - r;
        const int yy = cyi + oi;
        if ((unsigned)yy >= FH) continue;
        const float fi = exs[abs(oi)];               // broadcast LDS
        unsigned int* prow = (unsigned int*)&plane[(size_t)yy * FW];

        if (c0) {
            const int xx = cxi + oj0;
            if ((unsigned)xx < FW) {
                const float gv = fi * fj0;
                if (gv >= EPS_F32)
                    atomicMax(prow + xx, __float_as_uint(gv));
            }
        }
        if (c1) {
            const int xx = cxi + oj1;
            if ((unsigned)xx < FW) {
                const float gv = fi * fj1;
                if (gv >= EPS_F32)
                    atomicMax(prow + xx, __float_as_uint(gv));
            }
        }
    }
}

extern "C" void kernel_launch(void* const* d_in, const int* in_sizes, int n_in,
                              void* d_out, int out_size) {
    const float* gt = (const float*)d_in[0];
    float* out = (float*)d_out;

    float* heat  = out;
    float* boxes = out + HEAT_ELEMS;
    float* inds  = out + HEAT_ELEMS + BOXES_ELEMS;
    float* mask  = out + HEAT_ELEMS + BOXES_ELEMS + INDS_ELEMS;

    // One-time resources (streams/events only; no device memory)
    static cudaStream_t s1 = nullptr;
    static cudaEvent_t evM[NCHUNK];
    static cudaEvent_t evJoin = nullptr;
    if (s1 == nullptr) {
        cudaStreamCreateWithFlags(&s1, cudaStreamNonBlocking);
        for (int i = 0; i < NCHUNK; i++)
            cudaEventCreateWithFlags(&evM[i], cudaEventDisableTiming);
        cudaEventCreateWithFlags(&evJoin, cudaEventDisableTiming);
    }

    const size_t chunk_elems = (size_t)B_PER * NUM_CLASSES * FH * FW;

    // Fork/join pipeline: memset chunk i (origin stream) gates splat chunk i (s1).
    // splat_kernel writes every boxes/inds/mask slot itself, so only the
    // heatmap region needs zeroing.
    for (int i = 0; i < NCHUNK; i++) {
        cudaMemsetAsync(heat + (size_t)i * chunk_elems, 0,
                        chunk_elems * sizeof(float), 0);
        cudaEventRecord(evM[i], 0);
        cudaStreamWaitEvent(s1, evM[i], 0);
        splat_kernel<<<B_PER * NUM_MAX_OBJS, 128, 0, s1>>>(
            gt, heat, boxes, inds, mask, i * B_PER);
    }
    cudaEventRecord(evJoin, s1);
    cudaStreamWaitEvent(0, evJoin, 0);
}